// round 10
// baseline (speedup 1.0000x reference)
#include <cuda_runtime.h>

#define NA   9
#define NAA  81
#define HH   192
#define WWID 192
#define HW   (192*192)
#define CIN  32
#define MOUT 4
#define ND   9

typedef unsigned long long u64;

// scratch: mask pre-scaled by 81/sum (folds the mask_avg division)
__device__ float g_mask[NAA * HW];

__device__ __forceinline__ u64 fma2(u64 a, u64 b, u64 c) {
    u64 d; asm("fma.rn.f32x2 %0, %1, %2, %3;" : "=l"(d) : "l"(a), "l"(b), "l"(c)); return d;
}
__device__ __forceinline__ u64 mul2(u64 a, u64 b) {
    u64 d; asm("mul.rn.f32x2 %0, %1, %2;" : "=l"(d) : "l"(a), "l"(b)); return d;
}
__device__ __forceinline__ u64 pack2(float lo, float hi) {
    u64 d; asm("mov.b64 %0, {%1, %2};" : "=l"(d) : "f"(lo), "f"(hi)); return d;
}

__global__ void mask_scale_k(const float* __restrict__ mask) {
    int idx = blockIdx.x * 256 + threadIdx.x;
    if (idx >= HW) return;
    float s = 0.f;
    #pragma unroll 9
    for (int a = 0; a < NAA; a++) s += mask[a * HW + idx];
    float inv = 81.0f / s;
    #pragma unroll 9
    for (int a = 0; a < NAA; a++) g_mask[a * HW + idx] = mask[a * HW + idx] * inv;
}

// Fast (interior) path for d in [D0, D0+NDg). p,q,k fully unrolled;
// all offsets compile-time. W read as 2x LDS.128 (dup-packed).
template <int D0, int NDg>
__device__ __forceinline__ void accumulate_fast(const float* __restrict__ xc,
                                                const ulonglong2* __restrict__ sWd,
                                                int base, u64 acc[NDg][4]) {
    const float* b0 = xc + base;
    const float* m0 = g_mask + base;
    #pragma unroll
    for (int p = 0; p < 9; p++) {
        const int pp = 4 - p;
        #pragma unroll
        for (int q = 0; q < 9; q++) {
            const int qq = 4 - q;
            const int pq = p * 9 + q;
            ulonglong2 wA = sWd[pq * 2 + 0];   // (w0,w0),(w1,w1)  LDS.128 broadcast
            ulonglong2 wB = sWd[pq * 2 + 1];   // (w2,w2),(w3,w3)
            u64 mask2 = *(const u64*)(m0 + pq * HW);
            #pragma unroll
            for (int k = 0; k < NDg; k++) {
                const int d = D0 + k;                              // compile-time
                const int off = pq * HW + d * (pp * WWID + qq);    // literal
                u64 x2;
                if (((qq & 1) == 0) || ((d & 1) == 0)) {
                    x2 = *(const u64*)(b0 + off);
                } else {
                    x2 = pack2(b0[off], b0[off + 1]);
                }
                u64 t2 = mul2(mask2, x2);
                acc[k][0] = fma2(wA.x, t2, acc[k][0]);
                acc[k][1] = fma2(wA.y, t2, acc[k][1]);
                acc[k][2] = fma2(wB.x, t2, acc[k][2]);
                acc[k][3] = fma2(wB.y, t2, acc[k][3]);
            }
        }
    }
}

// Boundary path: rolled p-loop with full bounds checks.
template <int D0, int NDg>
__device__ __forceinline__ void accumulate_chk(const float* __restrict__ xc,
                                               const ulonglong2* __restrict__ sWd,
                                               int i, int j, u64 acc[NDg][4]) {
    const int base = i * WWID + j;
    #pragma unroll 1
    for (int p = 0; p < 9; p++) {
        const int pp = 4 - p;
        const int prow = pp * WWID;
        const float* bp = xc + base + p * 9 * HW;
        const float* mp = g_mask + base + p * 9 * HW;
        const float* bpd[NDg];
        int rowv[NDg];
        #pragma unroll
        for (int k = 0; k < NDg; k++) {
            const int d = D0 + k;
            bpd[k] = bp + d * prow;
            rowv[k] = i + d * pp;
        }
        #pragma unroll
        for (int q = 0; q < 9; q++) {
            const int qq = 4 - q;
            const int pq = p * 9 + q;
            ulonglong2 wA = sWd[pq * 2 + 0];
            ulonglong2 wB = sWd[pq * 2 + 1];
            u64 mask2 = *(const u64*)(mp + q * HW);
            #pragma unroll
            for (int k = 0; k < NDg; k++) {
                const int d = D0 + k;
                const int off = q * HW + d * qq;
                int colv = j + d * qq;
                bool rok = ((unsigned)rowv[k] < (unsigned)HH);
                u64 x2;
                if (((qq & 1) == 0) || ((d & 1) == 0)) {
                    bool ok = rok && ((unsigned)colv < (unsigned)(WWID - 1));
                    x2 = ok ? *(const u64*)(bpd[k] + off) : 0ull;
                } else {
                    float lo = (rok && (unsigned)colv       < (unsigned)WWID) ? bpd[k][off]     : 0.f;
                    float hi = (rok && (unsigned)(colv + 1) < (unsigned)WWID) ? bpd[k][off + 1] : 0.f;
                    x2 = pack2(lo, hi);
                }
                u64 t2 = mul2(mask2, x2);
                acc[k][0] = fma2(wA.x, t2, acc[k][0]);
                acc[k][1] = fma2(wA.y, t2, acc[k][1]);
                acc[k][2] = fma2(wB.x, t2, acc[k][2]);
                acc[k][3] = fma2(wB.y, t2, acc[k][3]);
            }
        }
    }
}

template <int D0, int NDg>
__device__ __forceinline__ void run_group(const float* __restrict__ xc,
                                          const ulonglong2* __restrict__ sWd,
                                          float* __restrict__ out,
                                          int c, int i, int j, bool interior) {
    u64 acc[NDg][4];
    #pragma unroll
    for (int k = 0; k < NDg; k++)
        #pragma unroll
        for (int m = 0; m < 4; m++) acc[k][m] = 0ull;

    const int base = i * WWID + j;
    if (interior) accumulate_fast<D0, NDg>(xc, sWd, base, acc);
    else          accumulate_chk<D0, NDg>(xc, sWd, i, j, acc);

    #pragma unroll
    for (int m = 0; m < 4; m++)
        #pragma unroll
        for (int k = 0; k < NDg; k++) {
            int dd = (D0 + 4) + k;   // d index in output (d = D0+k, stored at d+4)
            *(u64*)(out + (size_t)((c * MOUT + m) * ND + dd) * HW + base) = acc[k][m];
        }
}

__global__ __launch_bounds__(256, 4)
void build_cost_k(const float* __restrict__ x,
                  const float* __restrict__ W,
                  float* __restrict__ out) {
    // W dup-packed: sWd[pq*2+0] = {(w0,w0),(w1,w1)}, sWd[pq*2+1] = {(w2,w2),(w3,w3)}
    __shared__ __align__(16) ulonglong2 sWd[NAA * 2];
    const int tx = threadIdx.x;          // 0..15  (pixel pair in j)
    const int ty = threadIdx.y;          // 0..15  (row)
    const int tid = ty * 16 + tx;
    const int c = blockIdx.z >> 1;       // z = c*2 + g: both d-groups of a channel co-resident
    const int g = blockIdx.z & 1;
    const int j0 = blockIdx.x * 32;
    const int i0 = blockIdx.y * 16;

    for (int t = tid; t < NAA * MOUT; t += 256) {
        int m = t & 3, pq = t >> 2;
        float v = W[(c * MOUT + m) * NAA + pq];
        ((u64*)sWd)[pq * 4 + m] = pack2(v, v);
    }
    __syncthreads();

    const int i = i0 + ty;
    const int j = j0 + tx * 2;

    const float* xc = x + (size_t)c * NAA * HW;
    const bool interior = (i0 >= 16) && (i0 + 16 <= HH - 16) &&
                          (j0 >= 16) && (j0 + 32 <= WWID - 16);

    if (g == 0) run_group<-4, 5>(xc, sWd, out, c, i, j, interior);  // d = -4..0
    else        run_group< 1, 4>(xc, sWd, out, c, i, j, interior);  // d =  1..4
}

extern "C" void kernel_launch(void* const* d_in, const int* in_sizes, int n_in,
                              void* d_out, int out_size) {
    const float* x    = (const float*)d_in[0];  // [1,32,81,192,192]
    const float* mask = (const float*)d_in[1];  // [1,81,192,192]
    const float* W    = (const float*)d_in[2];  // [128,81]
    float* out = (float*)d_out;                 // [1,128,9,192,192]

    mask_scale_k<<<(HW + 255) / 256, 256>>>(mask);

    dim3 grid(WWID / 32, HH / 16, CIN * 2);  // z = c*2 + g
    dim3 block(16, 16);
    build_cost_k<<<grid, block>>>(x, W, out);
}

// round 11
// speedup vs baseline: 1.8112x; 1.8112x over previous
#include <cuda_runtime.h>

#define NA   9
#define NAA  81
#define HH   192
#define WWID 192
#define HW   (192*192)
#define CIN  32
#define MOUT 4
#define ND   9

typedef unsigned long long u64;

// scratch: mask pre-scaled by 81/sum (folds the mask_avg division)
__device__ float g_mask[NAA * HW];

__device__ __forceinline__ u64 fma2(u64 a, u64 b, u64 c) {
    u64 d; asm("fma.rn.f32x2 %0, %1, %2, %3;" : "=l"(d) : "l"(a), "l"(b), "l"(c)); return d;
}
__device__ __forceinline__ u64 mul2(u64 a, u64 b) {
    u64 d; asm("mul.rn.f32x2 %0, %1, %2;" : "=l"(d) : "l"(a), "l"(b)); return d;
}
__device__ __forceinline__ u64 pack2(float lo, float hi) {
    u64 d; asm("mov.b64 %0, {%1, %2};" : "=l"(d) : "f"(lo), "f"(hi)); return d;
}

__global__ void mask_scale_k(const float* __restrict__ mask) {
    int idx = blockIdx.x * 256 + threadIdx.x;
    if (idx >= HW) return;
    float s = 0.f;
    #pragma unroll 9
    for (int a = 0; a < NAA; a++) s += mask[a * HW + idx];
    float inv = 81.0f / s;
    #pragma unroll 9
    for (int a = 0; a < NAA; a++) g_mask[a * HW + idx] = mask[a * HW + idx] * inv;
}

// Fast (interior) path for d = D0 + 2*k, k in [0,NDg). All offsets compile-time.
// W: one LDS.128 per q (float4), duplicated into f32x2 lanes via ALU pack.
template <int D0, int NDg>
__device__ __forceinline__ void accumulate_fast(const float* __restrict__ xc,
                                                const float4* __restrict__ sWf,
                                                int base, u64 acc[NDg][4]) {
    const float* b0 = xc + base;
    const float* m0 = g_mask + base;
    #pragma unroll
    for (int p = 0; p < 9; p++) {
        const int pp = 4 - p;
        #pragma unroll
        for (int q = 0; q < 9; q++) {
            const int qq = 4 - q;
            const int pq = p * 9 + q;
            float4 w = sWf[pq];                 // 1x LDS.128 broadcast
            u64 w0 = pack2(w.x, w.x);
            u64 w1 = pack2(w.y, w.y);
            u64 w2 = pack2(w.z, w.z);
            u64 w3 = pack2(w.w, w.w);
            u64 mask2 = *(const u64*)(m0 + pq * HW);
            #pragma unroll
            for (int k = 0; k < NDg; k++) {
                const int d = D0 + 2 * k;                          // compile-time
                const int off = pq * HW + d * (pp * WWID + qq);    // literal
                u64 x2;
                if (((qq & 1) == 0) || ((d & 1) == 0)) {
                    x2 = *(const u64*)(b0 + off);
                } else {
                    x2 = pack2(b0[off], b0[off + 1]);
                }
                u64 t2 = mul2(mask2, x2);
                acc[k][0] = fma2(w0, t2, acc[k][0]);
                acc[k][1] = fma2(w1, t2, acc[k][1]);
                acc[k][2] = fma2(w2, t2, acc[k][2]);
                acc[k][3] = fma2(w3, t2, acc[k][3]);
            }
        }
    }
}

// Boundary path: rolled p-loop with full bounds checks.
template <int D0, int NDg>
__device__ __forceinline__ void accumulate_chk(const float* __restrict__ xc,
                                               const float4* __restrict__ sWf,
                                               int i, int j, u64 acc[NDg][4]) {
    const int base = i * WWID + j;
    #pragma unroll 1
    for (int p = 0; p < 9; p++) {
        const int pp = 4 - p;
        const int prow = pp * WWID;
        const float* bp = xc + base + p * 9 * HW;
        const float* mp = g_mask + base + p * 9 * HW;
        const float* bpd[NDg];
        int rowv[NDg];
        #pragma unroll
        for (int k = 0; k < NDg; k++) {
            const int d = D0 + 2 * k;
            bpd[k] = bp + d * prow;
            rowv[k] = i + d * pp;
        }
        #pragma unroll
        for (int q = 0; q < 9; q++) {
            const int qq = 4 - q;
            const int pq = p * 9 + q;
            float4 w = sWf[pq];
            u64 w0 = pack2(w.x, w.x);
            u64 w1 = pack2(w.y, w.y);
            u64 w2 = pack2(w.z, w.z);
            u64 w3 = pack2(w.w, w.w);
            u64 mask2 = *(const u64*)(mp + q * HW);
            #pragma unroll
            for (int k = 0; k < NDg; k++) {
                const int d = D0 + 2 * k;
                const int off = q * HW + d * qq;
                int colv = j + d * qq;
                bool rok = ((unsigned)rowv[k] < (unsigned)HH);
                u64 x2;
                if (((qq & 1) == 0) || ((d & 1) == 0)) {
                    bool ok = rok && ((unsigned)colv < (unsigned)(WWID - 1));
                    x2 = ok ? *(const u64*)(bpd[k] + off) : 0ull;
                } else {
                    float lo = (rok && (unsigned)colv       < (unsigned)WWID) ? bpd[k][off]     : 0.f;
                    float hi = (rok && (unsigned)(colv + 1) < (unsigned)WWID) ? bpd[k][off + 1] : 0.f;
                    x2 = pack2(lo, hi);
                }
                u64 t2 = mul2(mask2, x2);
                acc[k][0] = fma2(w0, t2, acc[k][0]);
                acc[k][1] = fma2(w1, t2, acc[k][1]);
                acc[k][2] = fma2(w2, t2, acc[k][2]);
                acc[k][3] = fma2(w3, t2, acc[k][3]);
            }
        }
    }
}

template <int D0, int NDg>
__device__ __forceinline__ void run_group(const float* __restrict__ xc,
                                          const float4* __restrict__ sWf,
                                          float* __restrict__ out,
                                          int c, int i, int j, bool interior) {
    u64 acc[NDg][4];
    #pragma unroll
    for (int k = 0; k < NDg; k++)
        #pragma unroll
        for (int m = 0; m < 4; m++) acc[k][m] = 0ull;

    const int base = i * WWID + j;
    if (interior) accumulate_fast<D0, NDg>(xc, sWf, base, acc);
    else          accumulate_chk<D0, NDg>(xc, sWf, i, j, acc);

    #pragma unroll
    for (int m = 0; m < 4; m++)
        #pragma unroll
        for (int k = 0; k < NDg; k++) {
            int dd = (D0 + 2 * k) + 4;   // output disparity slot
            *(u64*)(out + (size_t)((c * MOUT + m) * ND + dd) * HW + base) = acc[k][m];
        }
}

__global__ __launch_bounds__(256, 3)
void build_cost_k(const float* __restrict__ x,
                  const float* __restrict__ W,
                  float* __restrict__ out) {
    __shared__ __align__(16) float4 sWf[NAA];   // W[c*4+0..3][pq] as float4 per pq
    const int tx = threadIdx.x;          // 0..15  (pixel pair in j)
    const int ty = threadIdx.y;          // 0..15  (row)
    const int tid = ty * 16 + tx;
    const int c = blockIdx.z >> 1;       // z = c*2 + g: both parity groups co-resident
    const int g = blockIdx.z & 1;
    const int j0 = blockIdx.x * 32;
    const int i0 = blockIdx.y * 16;

    for (int t = tid; t < NAA * MOUT; t += 256) {
        int m = t & 3, pq = t >> 2;
        ((float*)sWf)[pq * 4 + m] = W[(c * MOUT + m) * NAA + pq];
    }
    __syncthreads();

    const int i = i0 + ty;
    const int j = j0 + tx * 2;

    const float* xc = x + (size_t)c * NAA * HW;
    const bool interior = (i0 >= 16) && (i0 + 16 <= HH - 16) &&
                          (j0 >= 16) && (j0 + 32 <= WWID - 16);

    if (g == 0) run_group<-4, 5>(xc, sWf, out, c, i, j, interior);  // d = -4,-2,0,2,4 (all aligned)
    else        run_group<-3, 4>(xc, sWf, out, c, i, j, interior);  // d = -3,-1,1,3
}

extern "C" void kernel_launch(void* const* d_in, const int* in_sizes, int n_in,
                              void* d_out, int out_size) {
    const float* x    = (const float*)d_in[0];  // [1,32,81,192,192]
    const float* mask = (const float*)d_in[1];  // [1,81,192,192]
    const float* W    = (const float*)d_in[2];  // [128,81]
    float* out = (float*)d_out;                 // [1,128,9,192,192]

    mask_scale_k<<<(HW + 255) / 256, 256>>>(mask);

    dim3 grid(WWID / 32, HH / 16, CIN * 2);  // z = c*2 + g
    dim3 block(16, 16);
    build_cost_k<<<grid, block>>>(x, W, out);
}

// round 12
// speedup vs baseline: 1.8294x; 1.0100x over previous
#include <cuda_runtime.h>

#define NA   9
#define NAA  81
#define HH   192
#define WWID 192
#define HW   (192*192)
#define CIN  32
#define MOUT 4
#define ND   9

typedef unsigned long long u64;

// scratch: mask pre-scaled by 81/sum (folds the mask_avg division)
__device__ float g_mask[NAA * HW];

__device__ __forceinline__ u64 fma2(u64 a, u64 b, u64 c) {
    u64 d; asm("fma.rn.f32x2 %0, %1, %2, %3;" : "=l"(d) : "l"(a), "l"(b), "l"(c)); return d;
}
__device__ __forceinline__ u64 mul2(u64 a, u64 b) {
    u64 d; asm("mul.rn.f32x2 %0, %1, %2;" : "=l"(d) : "l"(a), "l"(b)); return d;
}
__device__ __forceinline__ u64 pack2(float lo, float hi) {
    u64 d; asm("mov.b64 %0, {%1, %2};" : "=l"(d) : "f"(lo), "f"(hi)); return d;
}

__global__ void mask_scale_k(const float* __restrict__ mask) {
    int idx = blockIdx.x * 256 + threadIdx.x;
    if (idx >= HW) return;
    float s = 0.f;
    #pragma unroll 9
    for (int a = 0; a < NAA; a++) s += mask[a * HW + idx];
    float inv = 81.0f / s;
    #pragma unroll 9
    for (int a = 0; a < NAA; a++) g_mask[a * HW + idx] = mask[a * HW + idx] * inv;
}

// Fast (interior) path for one d-group G: dd = 3G..3G+2, d = dd-4.
// p,q,k fully unrolled; all offsets compile-time.
// W: ONE LDS.128 per tap (float4), duplicated to f32x2 lanes in the ALU pipe.
template <int G>
__device__ __forceinline__ void accumulate_fast(const float* __restrict__ xc,
                                                const float4* __restrict__ sWf,
                                                int base, u64 acc[3][4]) {
    const float* b0 = xc + base;
    const float* m0 = g_mask + base;
    #pragma unroll
    for (int p = 0; p < 9; p++) {
        const int pp = 4 - p;
        #pragma unroll
        for (int q = 0; q < 9; q++) {
            const int qq = 4 - q;
            const int pq = p * 9 + q;
            float4 w = sWf[pq];                 // 1x LDS.128 broadcast
            u64 w0 = pack2(w.x, w.x);
            u64 w1 = pack2(w.y, w.y);
            u64 w2 = pack2(w.z, w.z);
            u64 w3 = pack2(w.w, w.w);
            u64 mask2 = *(const u64*)(m0 + pq * HW);
            #pragma unroll
            for (int k = 0; k < 3; k++) {
                const int d = 3 * G + k - 4;                       // compile-time
                const int off = pq * HW + d * (pp * WWID + qq);    // literal
                u64 x2;
                if (((qq & 1) == 0) || ((d & 1) == 0)) {
                    x2 = *(const u64*)(b0 + off);
                } else {
                    x2 = pack2(b0[off], b0[off + 1]);
                }
                u64 t2 = mul2(mask2, x2);
                acc[k][0] = fma2(w0, t2, acc[k][0]);
                acc[k][1] = fma2(w1, t2, acc[k][1]);
                acc[k][2] = fma2(w2, t2, acc[k][2]);
                acc[k][3] = fma2(w3, t2, acc[k][3]);
            }
        }
    }
}

// Boundary path for d-group G: rolled p-loop with full bounds checks.
template <int G>
__device__ __forceinline__ void accumulate_chk(const float* __restrict__ xc,
                                               const float4* __restrict__ sWf,
                                               int i, int j, u64 acc[3][4]) {
    const int base = i * WWID + j;
    #pragma unroll 1
    for (int p = 0; p < 9; p++) {
        const int pp = 4 - p;
        const int prow = pp * WWID;
        const float* bp = xc + base + p * 9 * HW;
        const float* mp = g_mask + base + p * 9 * HW;
        const float* bpd[3];
        int rowv[3];
        #pragma unroll
        for (int k = 0; k < 3; k++) {
            const int d = 3 * G + k - 4;
            bpd[k] = bp + d * prow;
            rowv[k] = i + d * pp;
        }
        #pragma unroll
        for (int q = 0; q < 9; q++) {
            const int qq = 4 - q;
            const int pq = p * 9 + q;
            float4 w = sWf[pq];
            u64 w0 = pack2(w.x, w.x);
            u64 w1 = pack2(w.y, w.y);
            u64 w2 = pack2(w.z, w.z);
            u64 w3 = pack2(w.w, w.w);
            u64 mask2 = *(const u64*)(mp + q * HW);
            #pragma unroll
            for (int k = 0; k < 3; k++) {
                const int d = 3 * G + k - 4;
                const int off = q * HW + d * qq;
                int colv = j + d * qq;
                bool rok = ((unsigned)rowv[k] < (unsigned)HH);
                u64 x2;
                if (((qq & 1) == 0) || ((d & 1) == 0)) {
                    bool ok = rok && ((unsigned)colv < (unsigned)(WWID - 1));
                    x2 = ok ? *(const u64*)(bpd[k] + off) : 0ull;
                } else {
                    float lo = (rok && (unsigned)colv       < (unsigned)WWID) ? bpd[k][off]     : 0.f;
                    float hi = (rok && (unsigned)(colv + 1) < (unsigned)WWID) ? bpd[k][off + 1] : 0.f;
                    x2 = pack2(lo, hi);
                }
                u64 t2 = mul2(mask2, x2);
                acc[k][0] = fma2(w0, t2, acc[k][0]);
                acc[k][1] = fma2(w1, t2, acc[k][1]);
                acc[k][2] = fma2(w2, t2, acc[k][2]);
                acc[k][3] = fma2(w3, t2, acc[k][3]);
            }
        }
    }
}

__global__ __launch_bounds__(256, 4)
void build_cost_k(const float* __restrict__ x,
                  const float* __restrict__ W,
                  float* __restrict__ out) {
    __shared__ __align__(16) float4 sWf[NAA];   // W[c*4+0..3][pq] as float4 per pq
    const int tx = threadIdx.x;          // 0..15  (pixel pair in j)
    const int ty = threadIdx.y;          // 0..15  (row)
    const int tid = ty * 16 + tx;
    const int c = blockIdx.z / 3;        // z = c*3 + g: d-groups of a channel co-resident
    const int g = blockIdx.z % 3;
    const int j0 = blockIdx.x * 32;
    const int i0 = blockIdx.y * 16;

    for (int t = tid; t < NAA * MOUT; t += 256) {
        int m = t & 3, pq = t >> 2;
        ((float*)sWf)[pq * 4 + m] = W[(c * MOUT + m) * NAA + pq];
    }
    __syncthreads();

    const int i = i0 + ty;
    const int j = j0 + tx * 2;

    u64 acc[3][4];
    #pragma unroll
    for (int k = 0; k < 3; k++)
        #pragma unroll
        for (int m = 0; m < 4; m++) acc[k][m] = 0ull;

    const float* xc = x + (size_t)c * NAA * HW;

    const bool interior = (i0 >= 16) && (i0 + 16 <= HH - 16) &&
                          (j0 >= 16) && (j0 + 32 <= WWID - 16);
    const int base = i * WWID + j;
    if (interior) {
        if (g == 0)      accumulate_fast<0>(xc, sWf, base, acc);
        else if (g == 1) accumulate_fast<1>(xc, sWf, base, acc);
        else             accumulate_fast<2>(xc, sWf, base, acc);
    } else {
        if (g == 0)      accumulate_chk<0>(xc, sWf, i, j, acc);
        else if (g == 1) accumulate_chk<1>(xc, sWf, i, j, acc);
        else             accumulate_chk<2>(xc, sWf, i, j, acc);
    }

    #pragma unroll
    for (int m = 0; m < 4; m++)
        #pragma unroll
        for (int k = 0; k < 3; k++) {
            int dd = 3 * g + k;
            *(u64*)(out + (size_t)((c * MOUT + m) * ND + dd) * HW + base) = acc[k][m];
        }
}

extern "C" void kernel_launch(void* const* d_in, const int* in_sizes, int n_in,
                              void* d_out, int out_size) {
    const float* x    = (const float*)d_in[0];  // [1,32,81,192,192]
    const float* mask = (const float*)d_in[1];  // [1,81,192,192]
    const float* W    = (const float*)d_in[2];  // [128,81]
    float* out = (float*)d_out;                 // [1,128,9,192,192]

    mask_scale_k<<<(HW + 255) / 256, 256>>>(mask);

    dim3 grid(WWID / 32, HH / 16, CIN * 3);  // z = c*3 + g
    dim3 block(16, 16);
    build_cost_k<<<grid, block>>>(x, W, out);
}